// round 16
// baseline (speedup 1.0000x reference)
#include <cuda_runtime.h>
#include <cuda_fp16.h>
#include <cstdint>

// ---------------- SLAYER constants (double -> f32) --------------------------------
#define C2A 1.8096748360719190f   // 2*exp(-0.1)
#define CA2 0.8187307530779818f   // exp(-0.2)
#define CB1 0.2459603111156949f   // e*exp(-0.1)/10

// ---------------- scratch (static device memory; no allocation) -------------------
#define UMAX 13107200  // 25t * 4b * 32c * 64 * 64 floats (chunked SC1 slab)
__device__ float g_u[UMAX];
__device__ unsigned char g_s8a[13107200];
__device__ unsigned char g_s8b[13107200];
__device__ float g_part[8 * 400 * 512];
__device__ float g_state[30 * 131072];    // chunked scanpool IIR state
__device__ uint4 g_B1[5 * 4 * 32];        // SC1 frag weights (fused fp16 2-split)
__device__ uint4 g_B2[18 * 8 * 32];       // SC2 frag weights
__device__ uint4 g_B3[36 * 16 * 32];      // SC3 frag weights
__device__ uint4 g_B4[512 * 64 * 32];     // SF4a frag weights

// ---------------- mma.sync / ldmatrix helpers (fp16 in, f32 acc) -------------------
__device__ __forceinline__ void mmah(float (&c)[4], uint32_t a0, uint32_t a1,
                                     uint32_t a2, uint32_t a3, uint32_t b0, uint32_t b1) {
    asm volatile(
        "mma.sync.aligned.m16n8k16.row.col.f32.f16.f16.f32 "
        "{%0,%1,%2,%3}, {%4,%5,%6,%7}, {%8,%9}, {%0,%1,%2,%3};"
        : "+f"(c[0]), "+f"(c[1]), "+f"(c[2]), "+f"(c[3])
        : "r"(a0), "r"(a1), "r"(a2), "r"(a3), "r"(b0), "r"(b1));
}
__device__ __forceinline__ void ldm4(uint32_t (&a)[4], uint32_t addr) {
    asm volatile("ldmatrix.sync.aligned.m8n8.x4.shared.b16 {%0,%1,%2,%3}, [%4];"
                 : "=r"(a[0]), "=r"(a[1]), "=r"(a[2]), "=r"(a[3]) : "r"(addr));
}

// ---------------- weight 2-way fp16 split, both halves ----------------------------
__device__ __forceinline__ void wsplit2(float w, unsigned short& hi, unsigned short& lo) {
    __half h = __float2half_rn(w);
    float r = w - __half2float(h);
    hi = __half_as_ushort(h);
    lo = __half_as_ushort(__float2half_rn(r));
}

// ---------------- prep: SC1 frag weights (k = kw*2+ic, kw>=5 zero) ----------------
__global__ void prepB1_k(const float* __restrict__ wt, uint4* __restrict__ B) {
    int idx = blockIdx.x * blockDim.x + threadIdx.x;
    if (idx >= 5 * 4 * 32) return;
    int lane = idx & 31;
    int r = idx >> 5;
    int nt = r & 3;
    int kh = r >> 2;
    int g = lane >> 2, tg = lane & 3;
    int oc = nt * 8 + g;
    unsigned short v0[4], v1[4];
#pragma unroll
    for (int i = 0; i < 4; i++) {
        int k = tg * 2 + (i & 1) + (i >> 1) * 8;
        int kw = k >> 1, ic = k & 1;
        float w = (kw < 5) ? wt[((oc * 2 + ic) * 5 + kh) * 5 + kw] : 0.f;
        wsplit2(w, v0[i], v1[i]);
    }
    B[idx] = make_uint4((unsigned)v0[0] | ((unsigned)v0[1] << 16),
                        (unsigned)v0[2] | ((unsigned)v0[3] << 16),
                        (unsigned)v1[0] | ((unsigned)v1[1] << 16),
                        (unsigned)v1[2] | ((unsigned)v1[3] << 16));
}

// ---------------- prep: 3x3 conv frag weights -------------------------------------
template <int IC, int NTG, int NICB>
__global__ void prepB3_k(const float* __restrict__ wt, uint4* __restrict__ B, int total) {
    int idx = blockIdx.x * blockDim.x + threadIdx.x;
    if (idx >= total) return;
    int lane = idx & 31;
    int r = idx >> 5;
    int ntg = r % NTG;
    int it = r / NTG;
    int icb = it % NICB;
    int tap = it / NICB;
    int kh = tap / 3, kw = tap % 3;
    int g = lane >> 2, tg = lane & 3;
    int oc = ntg * 8 + g;
    unsigned short v0[4], v1[4];
#pragma unroll
    for (int i = 0; i < 4; i++) {
        int k = tg * 2 + (i & 1) + (i >> 1) * 8;
        int ic = icb * 16 + k;
        wsplit2(wt[((oc * IC + ic) * 3 + kh) * 3 + kw], v0[i], v1[i]);
    }
    B[idx] = make_uint4((unsigned)v0[0] | ((unsigned)v0[1] << 16),
                        (unsigned)v0[2] | ((unsigned)v0[3] << 16),
                        (unsigned)v1[0] | ((unsigned)v1[1] << 16),
                        (unsigned)v1[2] | ((unsigned)v1[3] << 16));
}

// ---------------- prep: SF4a frag weights -----------------------------------------
__global__ void prep4a_k(const float* __restrict__ w, uint4* __restrict__ B) {
    int idx = blockIdx.x * blockDim.x + threadIdx.x;
    if (idx >= 512 * 64 * 32) return;
    int lane = idx & 31;
    int r = idx >> 5;
    int ng = r & 63;
    int kb = r >> 6;
    int g = lane >> 2, tg = lane & 3;
    int n = ng * 8 + g;
    const float* wr = w + (size_t)n * 8192 + kb * 16 + tg * 2;
    float2 wa = *(const float2*)wr;
    float2 wb = *(const float2*)(wr + 8);
    float wv4[4] = {wa.x, wa.y, wb.x, wb.y};
    unsigned short v0[4], v1[4];
#pragma unroll
    for (int i = 0; i < 4; i++) wsplit2(wv4[i], v0[i], v1[i]);
    B[idx] = make_uint4((unsigned)v0[0] | ((unsigned)v0[1] << 16),
                        (unsigned)v0[2] | ((unsigned)v0[3] << 16),
                        (unsigned)v1[0] | ((unsigned)v1[1] << 16),
                        (unsigned)v1[2] | ((unsigned)v1[3] << 16));
}

// ---------------- SP0: pool(2x2)*11 on raw input + scan -> channel-last u8 --------
__global__ void scan_in_k(const float* __restrict__ sin, unsigned char* __restrict__ sout) {
    const int N = 32768;  // 4 b * 64 * 64 * 2 c
    int n = blockIdx.x * blockDim.x + threadIdx.x;
    if (n >= N) return;
    int c = n & 1, x = (n >> 1) & 63, y = (n >> 7) & 63, b = n >> 13;
    const float* p0 = sin + ((size_t)((b * 2 + c) * 128 + 2 * y) * 128 + 2 * x) * 100;
    const float* p1 = p0 + 100;
    const float* p2 = p0 + 12800;
    const float* p3 = p2 + 100;
    float a1 = 0.f, a2 = 0.f, cp = 0.f, r1 = 0.f, r2 = 0.f, sp = 0.f;
#pragma unroll 2
    for (int tc = 0; tc < 100; tc += 4) {
        float4 A = *(const float4*)(p0 + tc);
        float4 Bv = *(const float4*)(p1 + tc);
        float4 Cv = *(const float4*)(p2 + tc);
        float4 D = *(const float4*)(p3 + tc);
        float xs4[4] = {A.x + Bv.x + Cv.x + D.x, A.y + Bv.y + Cv.y + D.y,
                        A.z + Bv.z + Cv.z + D.z, A.w + Bv.w + Cv.w + D.w};
#pragma unroll
        for (int j = 0; j < 4; j++) {
            float xv = 11.0f * xs4[j];
            float uu = C2A * a1 - CA2 * a2 + CB1 * cp;
            float yy = C2A * r1 - CA2 * r2 + CB1 * sp;
            float ss = (uu - 20.0f * yy >= 10.0f) ? 1.0f : 0.0f;
            sout[(size_t)(tc + j) * N + n] = (unsigned char)ss;
            a2 = a1; a1 = uu; cp = xv;
            r2 = r1; r1 = yy; sp = ss;
        }
    }
}

// ---------------- fused conv-scan + pool + pooled-scan, t-chunked ------------------
template <int C, int H, int W, bool CF>
__global__ void scanpool_k(const float* __restrict__ u, unsigned char* __restrict__ s,
                           float* __restrict__ st, int t0, int TC) {
    constexpr int N = 4 * C * H * W;
    int n = blockIdx.x * blockDim.x + threadIdx.x;
    if (n >= N) return;
    int c = n % C;
    int r = n / C;
    int w = r % W, h = (r / W) % H, b = r / (W * H);
    const float* base = u + (size_t)b * 4 * H * W * C + ((size_t)(2 * h) * (2 * W) + 2 * w) * C + c;
    constexpr size_t ZST = (size_t)16 * H * W * C;  // per-t stride (4 images)
    const size_t oidx = CF ? (size_t)(((b * C + c) * H + h) * W + w) : (size_t)n;
    float y1[4], y2[4], xp[4], r1[4], r2[4], sp[4];
    float py1, py2, pxp, pr1, pr2, psp;
    if (t0 == 0) {
#pragma unroll
        for (int i = 0; i < 4; i++) { y1[i] = y2[i] = xp[i] = r1[i] = r2[i] = sp[i] = 0.f; }
        py1 = py2 = pxp = pr1 = pr2 = psp = 0.f;
    } else {
#pragma unroll
        for (int i = 0; i < 4; i++) {
            y1[i] = st[(size_t)(i) * N + n];
            y2[i] = st[(size_t)(4 + i) * N + n];
            xp[i] = st[(size_t)(8 + i) * N + n];
            r1[i] = st[(size_t)(12 + i) * N + n];
            r2[i] = st[(size_t)(16 + i) * N + n];
            sp[i] = st[(size_t)(20 + i) * N + n];
        }
        py1 = st[(size_t)24 * N + n]; py2 = st[(size_t)25 * N + n];
        pxp = st[(size_t)26 * N + n]; pr1 = st[(size_t)27 * N + n];
        pr2 = st[(size_t)28 * N + n]; psp = st[(size_t)29 * N + n];
    }
    for (int tl = 0; tl < TC; tl++) {
        float xin[4];
        xin[0] = base[0];
        xin[1] = base[C];
        xin[2] = base[2 * W * C];
        xin[3] = base[2 * W * C + C];
        float ssum = 0.f;
#pragma unroll
        for (int i = 0; i < 4; i++) {
            float yy = C2A * y1[i] - CA2 * y2[i] + CB1 * xp[i];
            float rr = C2A * r1[i] - CA2 * r2[i] + CB1 * sp[i];
            float si = (yy - 20.0f * rr >= 10.0f) ? 1.0f : 0.0f;
            y2[i] = y1[i]; y1[i] = yy; xp[i] = xin[i];
            r2[i] = r1[i]; r1[i] = rr; sp[i] = si;
            ssum += si;
        }
        float pu = C2A * py1 - CA2 * py2 + CB1 * pxp;
        float pr = C2A * pr1 - CA2 * pr2 + CB1 * psp;
        float ps = (pu - 20.0f * pr >= 10.0f) ? 1.0f : 0.0f;
        py2 = py1; py1 = pu; pxp = 11.0f * ssum;
        pr2 = pr1; pr1 = pr; psp = ps;
        s[(size_t)(t0 + tl) * N + oidx] = (unsigned char)ps;
        base += ZST;
    }
    if (t0 + TC < 100) {
#pragma unroll
        for (int i = 0; i < 4; i++) {
            st[(size_t)(i) * N + n] = y1[i];
            st[(size_t)(4 + i) * N + n] = y2[i];
            st[(size_t)(8 + i) * N + n] = xp[i];
            st[(size_t)(12 + i) * N + n] = r1[i];
            st[(size_t)(16 + i) * N + n] = r2[i];
            st[(size_t)(20 + i) * N + n] = sp[i];
        }
        st[(size_t)24 * N + n] = py1; st[(size_t)25 * N + n] = py2;
        st[(size_t)26 * N + n] = pxp; st[(size_t)27 * N + n] = pr1;
        st[(size_t)28 * N + n] = pr2; st[(size_t)29 * N + n] = psp;
    }
}

// ---------------- SC1: 5x5 conv, mma.sync, mt-split 8-warp CTAs (r14 winner) ------
__global__ void __launch_bounds__(256, 3)
conv1_k(const unsigned char* __restrict__ x, const uint4* __restrict__ B,
        float* __restrict__ u, int z0) {
    __shared__ __align__(16) __half xs[8 * 148];
    const int tid = threadIdx.x, lane = tid & 31, warp = tid >> 5;
    const int row = warp >> 1, ms = warp & 1;
    const int zl = blockIdx.y, R0 = blockIdx.x * 4;
    const unsigned char* xb = x + (size_t)(z0 + zl) * 8192;  // 64*64*2
    for (int idx = tid; idx < 8 * 72; idx += 256) {
        int sy = idx / 72, ix = idx % 72;
        int gy = R0 + sy - 2, gx = ix - 2;
        unsigned v0 = 0, v1 = 0;
        if (gy >= 0 && gy < 64 && gx >= 0 && gx < 64) {
            const unsigned char* p = xb + ((size_t)gy * 64 + gx) * 2;
            v0 = p[0]; v1 = p[1];
        }
        unsigned pack = (v0 ? 0x3C00u : 0u) | (v1 ? 0x3C000000u : 0u);
        *(unsigned*)&xs[sy * 148 + ix * 2] = pack;
    }
    __syncthreads();
    const int g = lane >> 2, tg = lane & 3;
    float acc[2][4][4];
#pragma unroll
    for (int mt = 0; mt < 2; mt++)
#pragma unroll
        for (int nt = 0; nt < 4; nt++)
#pragma unroll
            for (int i = 0; i < 4; i++) acc[mt][nt][i] = 0.f;
    int rbA[2];
#pragma unroll
    for (int mt = 0; mt < 2; mt++) rbA[mt] = row * 148 + ((ms * 2 + mt) * 16 + g) * 2;
#pragma unroll
    for (int kh = 0; kh < 5; kh++) {
        uint32_t a[2][4];
#pragma unroll
        for (int mt = 0; mt < 2; mt++) {
            int rb = rbA[mt] + kh * 148;
            a[mt][0] = *(const unsigned*)&xs[rb + tg * 2];
            a[mt][1] = *(const unsigned*)&xs[rb + (8 + tg) * 2];
            a[mt][2] = *(const unsigned*)&xs[rb + (tg + 4) * 2];
            a[mt][3] = *(const unsigned*)&xs[rb + (8 + tg + 4) * 2];
        }
#pragma unroll
        for (int nt = 0; nt < 4; nt++) {
            uint4 b = B[(kh * 4 + nt) * 32 + lane];
#pragma unroll
            for (int mt = 0; mt < 2; mt++)
                mmah(acc[mt][nt], a[mt][0], a[mt][1], a[mt][2], a[mt][3], b.x, b.y);
#pragma unroll
            for (int mt = 0; mt < 2; mt++)
                mmah(acc[mt][nt], a[mt][0], a[mt][1], a[mt][2], a[mt][3], b.z, b.w);
        }
    }
    float* ui = u + (size_t)zl * 4096 * 32;
#pragma unroll
    for (int mt = 0; mt < 2; mt++) {
        int p0 = (R0 + row) * 64 + (ms * 2 + mt) * 16 + g;
#pragma unroll
        for (int nt = 0; nt < 4; nt++) {
            int oc = nt * 8 + tg * 2;
            *(float2*)&ui[(size_t)p0 * 32 + oc] = make_float2(acc[mt][nt][0], acc[mt][nt][1]);
            *(float2*)&ui[(size_t)(p0 + 8) * 32 + oc] = make_float2(acc[mt][nt][2], acc[mt][nt][3]);
        }
    }
}

// ---------------- 3x3 convs (SC2/SC3), mma.sync, nt-split 8-warp CTAs -------------
// warps = MG x NG x 2 (ns); each warp = 4 m-tiles (64 px) x 2 ntg (16 oc).
// B-load count per block unchanged vs 4-warp config; A ldmatrix doubled (smem, cheap).
template <int IC, int OC, int W, int MG, int NG>
__global__ void __launch_bounds__(32 * MG * NG * 2, 3)
conv3_k(const unsigned char* __restrict__ x, const uint4* __restrict__ B,
        float* __restrict__ u, int z0) {
    constexpr int XP = IC + 8;
    constexpr int SXW = W + 2;
    constexpr int SH = 6;                 // 4 rows + 2 halo
    constexpr int NT = 32 * MG * NG * 2;
    constexpr int NICB = IC / 16, NTG = OC / 8;
    __shared__ __align__(16) __half xs[SH * SXW * XP];
    const int tid = threadIdx.x, lane = tid & 31, warp = tid >> 5;
    const int ns = warp & 1;
    const int wr = warp >> 1;
    const int mg = wr % MG, ng = wr / MG;
    const int zl = blockIdx.y, R0 = blockIdx.x * 4;
    const unsigned char* xb = x + (size_t)(z0 + zl) * W * W * IC;
    for (int idx = tid; idx < SH * SXW * (IC / 4); idx += NT) {
        int c4 = idx % (IC / 4);
        int r = idx / (IC / 4);
        int sx = r % SXW, sy = r / SXW;
        int gy = R0 + sy - 1, gx = sx - 1;
        unsigned v = 0;
        if (gy >= 0 && gy < W && gx >= 0 && gx < W)
            v = *(const unsigned*)(xb + ((size_t)gy * W + gx) * IC + c4 * 4);
        unsigned lo = ((v & 0xffu) ? 0x3C00u : 0u) | ((v & 0xff00u) ? 0x3C000000u : 0u);
        unsigned hi = ((v & 0xff0000u) ? 0x3C00u : 0u) | ((v & 0xff000000u) ? 0x3C000000u : 0u);
        *(uint2*)&xs[(sy * SXW + sx) * XP + c4 * 4] = make_uint2(lo, hi);
    }
    __syncthreads();
    uint32_t xsu = (uint32_t)__cvta_generic_to_shared(xs);
    const int l15 = lane & 15, lc8 = (lane >> 4) * 8;
    uint32_t abase[4];
#pragma unroll
    for (int mt = 0; mt < 4; mt++) {
        int p = mg * 64 + mt * 16 + l15;
        int ly = p / W, lx = p % W;
        abase[mt] = xsu + ((ly * SXW + lx) * XP + lc8) * 2;
    }
    float acc[4][2][4];
#pragma unroll
    for (int mt = 0; mt < 4; mt++)
#pragma unroll
        for (int nt = 0; nt < 2; nt++)
#pragma unroll
            for (int i = 0; i < 4; i++) acc[mt][nt][i] = 0.f;
#pragma unroll
    for (int kh = 0; kh < 3; kh++)
#pragma unroll
        for (int kw = 0; kw < 3; kw++)
#pragma unroll
            for (int icb = 0; icb < NICB; icb++) {
                const int it = (kh * 3 + kw) * NICB + icb;
                const int aoff = ((kh * SXW + kw) * XP + icb * 16) * 2;
                uint32_t a[4][4];
#pragma unroll
                for (int mt = 0; mt < 4; mt++) ldm4(a[mt], abase[mt] + aoff);
#pragma unroll
                for (int nt = 0; nt < 2; nt++) {
                    int ntg = ng * 4 + ns * 2 + nt;
                    uint4 b = B[(it * NTG + ntg) * 32 + lane];
#pragma unroll
                    for (int mt = 0; mt < 4; mt++)
                        mmah(acc[mt][nt], a[mt][0], a[mt][1], a[mt][2], a[mt][3], b.x, b.y);
#pragma unroll
                    for (int mt = 0; mt < 4; mt++)
                        mmah(acc[mt][nt], a[mt][0], a[mt][1], a[mt][2], a[mt][3], b.z, b.w);
                }
            }
    float* ui = u + (size_t)zl * W * W * OC;
    const int g = lane >> 2, tg = lane & 3;
#pragma unroll
    for (int mt = 0; mt < 4; mt++) {
        int p0 = R0 * W + mg * 64 + mt * 16 + g;
#pragma unroll
        for (int nt = 0; nt < 2; nt++) {
            int oc = ng * 32 + (ns * 2 + nt) * 8 + tg * 2;
            *(float2*)&ui[(size_t)p0 * OC + oc] = make_float2(acc[mt][nt][0], acc[mt][nt][1]);
            *(float2*)&ui[(size_t)(p0 + 8) * OC + oc] = make_float2(acc[mt][nt][2], acc[mt][nt][3]);
        }
    }
}

// ---------------- SF4a tensor-core GEMM: [400x8192](u8) x [8192->512], split-K=8 --
__global__ void __launch_bounds__(256)
gemm4am_k(const unsigned char* __restrict__ x, const uint4* __restrict__ B,
          float* __restrict__ part) {
    constexpr int KP = 72;  // fp16 pitch
    __shared__ __align__(16) __half as[128 * KP];
    const int tid = threadIdx.x, lane = tid & 31, warp = tid >> 5;
    const int mg = warp & 1, ng4 = warp >> 1;
    const int M0 = blockIdx.y * 128, N0 = blockIdx.x * 128;
    const int k00 = blockIdx.z * 1024;
    const int l15 = lane & 15, lc8 = (lane >> 4) * 8;
    const int g = lane >> 2, tg = lane & 3;
    uint32_t asu = (uint32_t)__cvta_generic_to_shared(as);
    float acc[4][4][4];
#pragma unroll
    for (int mt = 0; mt < 4; mt++)
#pragma unroll
        for (int nt = 0; nt < 4; nt++)
#pragma unroll
            for (int i = 0; i < 4; i++) acc[mt][nt][i] = 0.f;

    for (int k0 = k00; k0 < k00 + 1024; k0 += 64) {
#pragma unroll
        for (int i = 0; i < 8; i++) {
            int pos = tid + i * 256;
            int row = pos >> 4, c4 = pos & 15;
            uchar4 v = *(const uchar4*)(x + (size_t)(M0 + row) * 8192 + k0 + c4 * 4);
            unsigned lo = (v.x ? 0x3C00u : 0u) | (v.y ? 0x3C000000u : 0u);
            unsigned hi = (v.z ? 0x3C00u : 0u) | (v.w ? 0x3C000000u : 0u);
            *(uint2*)&as[row * KP + c4 * 4] = make_uint2(lo, hi);
        }
        __syncthreads();
#pragma unroll
        for (int kc = 0; kc < 4; kc++) {
            int kb = (k0 >> 4) + kc;
            uint32_t a[4][4];
#pragma unroll
            for (int mt = 0; mt < 4; mt++)
                ldm4(a[mt], asu + (((mg * 64 + mt * 16 + l15) * KP) + lc8 + kc * 16) * 2);
#pragma unroll
            for (int nt = 0; nt < 4; nt++) {
                int ngg = (N0 >> 3) + ng4 * 4 + nt;
                uint4 b = B[(kb * 64 + ngg) * 32 + lane];
#pragma unroll
                for (int mt = 0; mt < 4; mt++)
                    mmah(acc[mt][nt], a[mt][0], a[mt][1], a[mt][2], a[mt][3], b.x, b.y);
#pragma unroll
                for (int mt = 0; mt < 4; mt++)
                    mmah(acc[mt][nt], a[mt][0], a[mt][1], a[mt][2], a[mt][3], b.z, b.w);
            }
        }
        __syncthreads();
    }
    float* pb = part + (size_t)blockIdx.z * 204800;
#pragma unroll
    for (int mt = 0; mt < 4; mt++) {
        int z0 = M0 + mg * 64 + mt * 16 + g;
#pragma unroll
        for (int nt = 0; nt < 4; nt++) {
            int col = N0 + ng4 * 32 + nt * 8 + tg * 2;
            if (z0 < 400)
                *(float2*)&pb[(size_t)z0 * 512 + col] = make_float2(acc[mt][nt][0], acc[mt][nt][1]);
            if (z0 + 8 < 400)
                *(float2*)&pb[(size_t)(z0 + 8) * 512 + col] = make_float2(acc[mt][nt][2], acc[mt][nt][3]);
        }
    }
}

// ---------------- SF4a fused reduce(8)+scan, smem-staged (64 neurons/block) -------
__global__ void __launch_bounds__(256) scan4a_k(const float* __restrict__ part,
                                                unsigned char* __restrict__ s) {
    __shared__ float us[64 * 101];
    const int tid = threadIdx.x;
    const int nb = blockIdx.x * 64;
    for (int i = tid; i < 6400; i += 256) {
        int t = i >> 6, nl = i & 63;
        size_t base = (size_t)t * 2048 + nb + nl;
        float c = 0.f;
#pragma unroll
        for (int j = 0; j < 8; j++) c += part[(size_t)j * 204800 + base];
        us[nl * 101 + t] = c;
    }
    __syncthreads();
    if (tid < 64) {
        float p1 = 0.f, p2 = 0.f, cp = 0.f, r1 = 0.f, r2 = 0.f, sp = 0.f;
        const float* un = &us[tid * 101];
        for (int t = 0; t < 100; t++) {
            float c = un[t];
            float uu = C2A * p1 - CA2 * p2 + CB1 * cp;
            float yy = C2A * r1 - CA2 * r2 + CB1 * sp;
            float ss = (uu - 20.0f * yy >= 10.0f) ? 1.0f : 0.0f;
            s[(size_t)t * 2048 + nb + tid] = (unsigned char)ss;
            p2 = p1; p1 = uu; cp = c;
            r2 = r1; r1 = yy; sp = ss;
        }
    }
}

// ---------------- SF4b GEMM: [400 x 512](u8) * [512 -> 11] -------------------------
__global__ void gemm4b_k(const unsigned char* __restrict__ x, const float* __restrict__ w,
                         float* __restrict__ u) {
    int tb = blockIdx.x;
    int wid = threadIdx.x >> 5, lid = threadIdx.x & 31;  // 11 warps
    const unsigned char* xr = x + (size_t)tb * 512;
    const float* wr = w + (size_t)wid * 512;
    float s = 0.f;
    for (int k = lid; k < 512; k += 32) s += (float)xr[k] * wr[k];
#pragma unroll
    for (int off = 16; off; off >>= 1) s += __shfl_xor_sync(0xffffffffu, s, off);
    if (lid == 0) u[tb * 11 + wid] = s;
}

// ---------------- final scan (smem-staged): u4b [t][b*11+o] -> d_out [b][11][t] ----
__global__ void scan_out_k(const float* __restrict__ u, float* __restrict__ out) {
    __shared__ float us[44 * 101];
    const int tid = threadIdx.x;
    for (int i = tid; i < 4400; i += 128) {
        int t = i / 44, n = i % 44;
        us[n * 101 + t] = u[i];
    }
    __syncthreads();
    if (tid < 44) {
        int b = tid / 11, o = tid % 11;
        const float* un = &us[tid * 101];
        float a1 = 0.f, a2 = 0.f, cp = 0.f, r1 = 0.f, r2 = 0.f, sp = 0.f;
        for (int t = 0; t < 100; t++) {
            float c = un[t];
            float uu = C2A * a1 - CA2 * a2 + CB1 * cp;
            float yy = C2A * r1 - CA2 * r2 + CB1 * sp;
            float ss = (uu - 20.0f * yy >= 10.0f) ? 1.0f : 0.0f;
            out[(b * 11 + o) * 100 + t] = ss;
            a2 = a1; a1 = uu; cp = c;
            r2 = r1; r1 = yy; sp = ss;
        }
    }
}

// ---------------- driver ----------------------------------------------------------
extern "C" void kernel_launch(void* const* d_in, const int* in_sizes, int n_in,
                              void* d_out, int out_size) {
    const float* s_in = (const float*)d_in[0];
    const float* w1   = (const float*)d_in[1];
    const float* w2   = (const float*)d_in[2];
    const float* w3   = (const float*)d_in[3];
    const float* wf4a = (const float*)d_in[4];
    const float* wf4b = (const float*)d_in[5];
    float* out = (float*)d_out;

    float *u, *pp, *st;
    unsigned char *sa, *sb;
    uint4 *b1, *b2, *b3, *b4;
    cudaGetSymbolAddress((void**)&u, g_u);
    cudaGetSymbolAddress((void**)&sa, g_s8a);
    cudaGetSymbolAddress((void**)&sb, g_s8b);
    cudaGetSymbolAddress((void**)&pp, g_part);
    cudaGetSymbolAddress((void**)&st, g_state);
    cudaGetSymbolAddress((void**)&b1, g_B1);
    cudaGetSymbolAddress((void**)&b2, g_B2);
    cudaGetSymbolAddress((void**)&b3, g_B3);
    cudaGetSymbolAddress((void**)&b4, g_B4);

    // launch order arranged so index 3 (the profiled launch) is conv1_k.
    prep4a_k<<<4096, 256>>>(wf4a, b4);                    // 0
    scan_in_k<<<128, 256>>>(s_in, sa);                    // 1
    prepB1_k<<<3, 256>>>(w1, b1);                         // 2

    // SC1: 4 t-chunks of 25; u slab (52 MB) stays L2-resident between conv and scan
    for (int ch = 0; ch < 4; ch++) {
        conv1_k<<<dim3(16, 100), 256>>>(sa, b1, u, ch * 100);   // ch0 -> index 3
        scanpool_k<32, 32, 32, false><<<512, 256>>>(u, sb, st, ch * 25, 25);
    }
    prepB3_k<32, 8, 2><<<18, 256>>>(w2, b2, 4608);
    prepB3_k<64, 16, 4><<<72, 256>>>(w3, b3, 18432);
    // SC2: 2 t-chunks of 50; u slab 52 MB
    for (int ch = 0; ch < 2; ch++) {
        conv3_k<32, 64, 32, 2, 2><<<dim3(8, 200), 256>>>(sb, b2, u, ch * 200);
        scanpool_k<64, 16, 16, false><<<256, 256>>>(u, sa, st, ch * 50, 50);
    }
    // SC3: single chunk (u = 52 MB total)
    conv3_k<64, 128, 16, 1, 4><<<dim3(4, 400), 256>>>(sa, b3, u, 0);
    scanpool_k<128, 8, 8, true><<<64, 256>>>(u, sb, st, 0, 100);

    // SF4a: tensor-core GEMM split-K=8 -> part; fused smem reduce+scan -> sa
    gemm4am_k<<<dim3(4, 4, 8), 256>>>(sb, b4, pp);
    scan4a_k<<<32, 256>>>(pp, sa);
    // SF4b: GEMM -> u : [z][11]; final scan -> d_out [4][11][100]
    gemm4b_k<<<400, 352>>>(sa, wf4b, u);
    scan_out_k<<<1, 128>>>(u, out);
}

// round 17
// speedup vs baseline: 1.2011x; 1.2011x over previous
#include <cuda_runtime.h>
#include <cuda_fp16.h>
#include <cstdint>

// ---------------- SLAYER constants (double -> f32) --------------------------------
#define C2A 1.8096748360719190f   // 2*exp(-0.1)
#define CA2 0.8187307530779818f   // exp(-0.2)
#define CB1 0.2459603111156949f   // e*exp(-0.1)/10

// ---------------- scratch (static device memory; no allocation) -------------------
#define UMAX 13107200  // 25t * 4b * 32c * 64 * 64 floats (chunked SC1 slab)
__device__ float g_u[UMAX];
__device__ unsigned char g_s8a[13107200];
__device__ unsigned char g_s8b[13107200];
__device__ float g_part[8 * 400 * 512];
__device__ float g_state[30 * 131072];    // chunked scanpool IIR state
__device__ uint4 g_B1[5 * 4 * 32];        // SC1 frag weights (fused fp16 2-split)
__device__ uint4 g_B2[18 * 8 * 32];       // SC2 frag weights
__device__ uint4 g_B3[36 * 16 * 32];      // SC3 frag weights
__device__ uint4 g_B4[512 * 64 * 32];     // SF4a frag weights

// ---------------- mma.sync / ldmatrix helpers (fp16 in, f32 acc) -------------------
__device__ __forceinline__ void mmah(float (&c)[4], uint32_t a0, uint32_t a1,
                                     uint32_t a2, uint32_t a3, uint32_t b0, uint32_t b1) {
    asm volatile(
        "mma.sync.aligned.m16n8k16.row.col.f32.f16.f16.f32 "
        "{%0,%1,%2,%3}, {%4,%5,%6,%7}, {%8,%9}, {%0,%1,%2,%3};"
        : "+f"(c[0]), "+f"(c[1]), "+f"(c[2]), "+f"(c[3])
        : "r"(a0), "r"(a1), "r"(a2), "r"(a3), "r"(b0), "r"(b1));
}
__device__ __forceinline__ void ldm4(uint32_t (&a)[4], uint32_t addr) {
    asm volatile("ldmatrix.sync.aligned.m8n8.x4.shared.b16 {%0,%1,%2,%3}, [%4];"
                 : "=r"(a[0]), "=r"(a[1]), "=r"(a[2]), "=r"(a[3]) : "r"(addr));
}

// ---------------- weight 2-way fp16 split, both halves ----------------------------
__device__ __forceinline__ void wsplit2(float w, unsigned short& hi, unsigned short& lo) {
    __half h = __float2half_rn(w);
    float r = w - __half2float(h);
    hi = __half_as_ushort(h);
    lo = __half_as_ushort(__float2half_rn(r));
}

// ---------------- prep: SC1 frag weights (k = kw*2+ic, kw>=5 zero) ----------------
__global__ void prepB1_k(const float* __restrict__ wt, uint4* __restrict__ B) {
    int idx = blockIdx.x * blockDim.x + threadIdx.x;
    if (idx >= 5 * 4 * 32) return;
    int lane = idx & 31;
    int r = idx >> 5;
    int nt = r & 3;
    int kh = r >> 2;
    int g = lane >> 2, tg = lane & 3;
    int oc = nt * 8 + g;
    unsigned short v0[4], v1[4];
#pragma unroll
    for (int i = 0; i < 4; i++) {
        int k = tg * 2 + (i & 1) + (i >> 1) * 8;
        int kw = k >> 1, ic = k & 1;
        float w = (kw < 5) ? wt[((oc * 2 + ic) * 5 + kh) * 5 + kw] : 0.f;
        wsplit2(w, v0[i], v1[i]);
    }
    B[idx] = make_uint4((unsigned)v0[0] | ((unsigned)v0[1] << 16),
                        (unsigned)v0[2] | ((unsigned)v0[3] << 16),
                        (unsigned)v1[0] | ((unsigned)v1[1] << 16),
                        (unsigned)v1[2] | ((unsigned)v1[3] << 16));
}

// ---------------- prep: 3x3 conv frag weights -------------------------------------
template <int IC, int NTG, int NICB>
__global__ void prepB3_k(const float* __restrict__ wt, uint4* __restrict__ B, int total) {
    int idx = blockIdx.x * blockDim.x + threadIdx.x;
    if (idx >= total) return;
    int lane = idx & 31;
    int r = idx >> 5;
    int ntg = r % NTG;
    int it = r / NTG;
    int icb = it % NICB;
    int tap = it / NICB;
    int kh = tap / 3, kw = tap % 3;
    int g = lane >> 2, tg = lane & 3;
    int oc = ntg * 8 + g;
    unsigned short v0[4], v1[4];
#pragma unroll
    for (int i = 0; i < 4; i++) {
        int k = tg * 2 + (i & 1) + (i >> 1) * 8;
        int ic = icb * 16 + k;
        wsplit2(wt[((oc * IC + ic) * 3 + kh) * 3 + kw], v0[i], v1[i]);
    }
    B[idx] = make_uint4((unsigned)v0[0] | ((unsigned)v0[1] << 16),
                        (unsigned)v0[2] | ((unsigned)v0[3] << 16),
                        (unsigned)v1[0] | ((unsigned)v1[1] << 16),
                        (unsigned)v1[2] | ((unsigned)v1[3] << 16));
}

// ---------------- prep: SF4a frag weights -----------------------------------------
__global__ void prep4a_k(const float* __restrict__ w, uint4* __restrict__ B) {
    int idx = blockIdx.x * blockDim.x + threadIdx.x;
    if (idx >= 512 * 64 * 32) return;
    int lane = idx & 31;
    int r = idx >> 5;
    int ng = r & 63;
    int kb = r >> 6;
    int g = lane >> 2, tg = lane & 3;
    int n = ng * 8 + g;
    const float* wr = w + (size_t)n * 8192 + kb * 16 + tg * 2;
    float2 wa = *(const float2*)wr;
    float2 wb = *(const float2*)(wr + 8);
    float wv4[4] = {wa.x, wa.y, wb.x, wb.y};
    unsigned short v0[4], v1[4];
#pragma unroll
    for (int i = 0; i < 4; i++) wsplit2(wv4[i], v0[i], v1[i]);
    B[idx] = make_uint4((unsigned)v0[0] | ((unsigned)v0[1] << 16),
                        (unsigned)v0[2] | ((unsigned)v0[3] << 16),
                        (unsigned)v1[0] | ((unsigned)v1[1] << 16),
                        (unsigned)v1[2] | ((unsigned)v1[3] << 16));
}

// ---------------- SP0: pool(2x2)*11 on raw input + scan -> channel-last u8 --------
__global__ void scan_in_k(const float* __restrict__ sin, unsigned char* __restrict__ sout) {
    const int N = 32768;  // 4 b * 64 * 64 * 2 c
    int n = blockIdx.x * blockDim.x + threadIdx.x;
    if (n >= N) return;
    int c = n & 1, x = (n >> 1) & 63, y = (n >> 7) & 63, b = n >> 13;
    const float* p0 = sin + ((size_t)((b * 2 + c) * 128 + 2 * y) * 128 + 2 * x) * 100;
    const float* p1 = p0 + 100;
    const float* p2 = p0 + 12800;
    const float* p3 = p2 + 100;
    float a1 = 0.f, a2 = 0.f, cp = 0.f, r1 = 0.f, r2 = 0.f, sp = 0.f;
#pragma unroll 2
    for (int tc = 0; tc < 100; tc += 4) {
        float4 A = *(const float4*)(p0 + tc);
        float4 Bv = *(const float4*)(p1 + tc);
        float4 Cv = *(const float4*)(p2 + tc);
        float4 D = *(const float4*)(p3 + tc);
        float xs4[4] = {A.x + Bv.x + Cv.x + D.x, A.y + Bv.y + Cv.y + D.y,
                        A.z + Bv.z + Cv.z + D.z, A.w + Bv.w + Cv.w + D.w};
#pragma unroll
        for (int j = 0; j < 4; j++) {
            float xv = 11.0f * xs4[j];
            float uu = C2A * a1 - CA2 * a2 + CB1 * cp;
            float yy = C2A * r1 - CA2 * r2 + CB1 * sp;
            float ss = (uu - 20.0f * yy >= 10.0f) ? 1.0f : 0.0f;
            sout[(size_t)(tc + j) * N + n] = (unsigned char)ss;
            a2 = a1; a1 = uu; cp = xv;
            r2 = r1; r1 = yy; sp = ss;
        }
    }
}

// ---------------- fused conv-scan + pool + pooled-scan, t-chunked ------------------
template <int C, int H, int W, bool CF>
__global__ void scanpool_k(const float* __restrict__ u, unsigned char* __restrict__ s,
                           float* __restrict__ st, int t0, int TC) {
    constexpr int N = 4 * C * H * W;
    int n = blockIdx.x * blockDim.x + threadIdx.x;
    if (n >= N) return;
    int c = n % C;
    int r = n / C;
    int w = r % W, h = (r / W) % H, b = r / (W * H);
    const float* base = u + (size_t)b * 4 * H * W * C + ((size_t)(2 * h) * (2 * W) + 2 * w) * C + c;
    constexpr size_t ZST = (size_t)16 * H * W * C;  // per-t stride (4 images)
    const size_t oidx = CF ? (size_t)(((b * C + c) * H + h) * W + w) : (size_t)n;
    float y1[4], y2[4], xp[4], r1[4], r2[4], sp[4];
    float py1, py2, pxp, pr1, pr2, psp;
    if (t0 == 0) {
#pragma unroll
        for (int i = 0; i < 4; i++) { y1[i] = y2[i] = xp[i] = r1[i] = r2[i] = sp[i] = 0.f; }
        py1 = py2 = pxp = pr1 = pr2 = psp = 0.f;
    } else {
#pragma unroll
        for (int i = 0; i < 4; i++) {
            y1[i] = st[(size_t)(i) * N + n];
            y2[i] = st[(size_t)(4 + i) * N + n];
            xp[i] = st[(size_t)(8 + i) * N + n];
            r1[i] = st[(size_t)(12 + i) * N + n];
            r2[i] = st[(size_t)(16 + i) * N + n];
            sp[i] = st[(size_t)(20 + i) * N + n];
        }
        py1 = st[(size_t)24 * N + n]; py2 = st[(size_t)25 * N + n];
        pxp = st[(size_t)26 * N + n]; pr1 = st[(size_t)27 * N + n];
        pr2 = st[(size_t)28 * N + n]; psp = st[(size_t)29 * N + n];
    }
    for (int tl = 0; tl < TC; tl++) {
        float xin[4];
        xin[0] = base[0];
        xin[1] = base[C];
        xin[2] = base[2 * W * C];
        xin[3] = base[2 * W * C + C];
        float ssum = 0.f;
#pragma unroll
        for (int i = 0; i < 4; i++) {
            float yy = C2A * y1[i] - CA2 * y2[i] + CB1 * xp[i];
            float rr = C2A * r1[i] - CA2 * r2[i] + CB1 * sp[i];
            float si = (yy - 20.0f * rr >= 10.0f) ? 1.0f : 0.0f;
            y2[i] = y1[i]; y1[i] = yy; xp[i] = xin[i];
            r2[i] = r1[i]; r1[i] = rr; sp[i] = si;
            ssum += si;
        }
        float pu = C2A * py1 - CA2 * py2 + CB1 * pxp;
        float pr = C2A * pr1 - CA2 * pr2 + CB1 * psp;
        float ps = (pu - 20.0f * pr >= 10.0f) ? 1.0f : 0.0f;
        py2 = py1; py1 = pu; pxp = 11.0f * ssum;
        pr2 = pr1; pr1 = pr; psp = ps;
        s[(size_t)(t0 + tl) * N + oidx] = (unsigned char)ps;
        base += ZST;
    }
    if (t0 + TC < 100) {
#pragma unroll
        for (int i = 0; i < 4; i++) {
            st[(size_t)(i) * N + n] = y1[i];
            st[(size_t)(4 + i) * N + n] = y2[i];
            st[(size_t)(8 + i) * N + n] = xp[i];
            st[(size_t)(12 + i) * N + n] = r1[i];
            st[(size_t)(16 + i) * N + n] = r2[i];
            st[(size_t)(20 + i) * N + n] = sp[i];
        }
        st[(size_t)24 * N + n] = py1; st[(size_t)25 * N + n] = py2;
        st[(size_t)26 * N + n] = pxp; st[(size_t)27 * N + n] = pr1;
        st[(size_t)28 * N + n] = pr2; st[(size_t)29 * N + n] = psp;
    }
}

// ---------------- SC1: 5x5 conv, mma.sync, mt-split 8-warp CTAs (r14 winner) ------
__global__ void __launch_bounds__(256, 3)
conv1_k(const unsigned char* __restrict__ x, const uint4* __restrict__ B,
        float* __restrict__ u, int z0) {
    __shared__ __align__(16) __half xs[8 * 148];
    const int tid = threadIdx.x, lane = tid & 31, warp = tid >> 5;
    const int row = warp >> 1, ms = warp & 1;
    const int zl = blockIdx.y, R0 = blockIdx.x * 4;
    const unsigned char* xb = x + (size_t)(z0 + zl) * 8192;  // 64*64*2
    for (int idx = tid; idx < 8 * 72; idx += 256) {
        int sy = idx / 72, ix = idx % 72;
        int gy = R0 + sy - 2, gx = ix - 2;
        unsigned v0 = 0, v1 = 0;
        if (gy >= 0 && gy < 64 && gx >= 0 && gx < 64) {
            const unsigned char* p = xb + ((size_t)gy * 64 + gx) * 2;
            v0 = p[0]; v1 = p[1];
        }
        unsigned pack = (v0 ? 0x3C00u : 0u) | (v1 ? 0x3C000000u : 0u);
        *(unsigned*)&xs[sy * 148 + ix * 2] = pack;
    }
    __syncthreads();
    const int g = lane >> 2, tg = lane & 3;
    float acc[2][4][4];
#pragma unroll
    for (int mt = 0; mt < 2; mt++)
#pragma unroll
        for (int nt = 0; nt < 4; nt++)
#pragma unroll
            for (int i = 0; i < 4; i++) acc[mt][nt][i] = 0.f;
    int rbA[2];
#pragma unroll
    for (int mt = 0; mt < 2; mt++) rbA[mt] = row * 148 + ((ms * 2 + mt) * 16 + g) * 2;
#pragma unroll
    for (int kh = 0; kh < 5; kh++) {
        uint32_t a[2][4];
#pragma unroll
        for (int mt = 0; mt < 2; mt++) {
            int rb = rbA[mt] + kh * 148;
            a[mt][0] = *(const unsigned*)&xs[rb + tg * 2];
            a[mt][1] = *(const unsigned*)&xs[rb + (8 + tg) * 2];
            a[mt][2] = *(const unsigned*)&xs[rb + (tg + 4) * 2];
            a[mt][3] = *(const unsigned*)&xs[rb + (8 + tg + 4) * 2];
        }
#pragma unroll
        for (int nt = 0; nt < 4; nt++) {
            uint4 b = B[(kh * 4 + nt) * 32 + lane];
#pragma unroll
            for (int mt = 0; mt < 2; mt++)
                mmah(acc[mt][nt], a[mt][0], a[mt][1], a[mt][2], a[mt][3], b.x, b.y);
#pragma unroll
            for (int mt = 0; mt < 2; mt++)
                mmah(acc[mt][nt], a[mt][0], a[mt][1], a[mt][2], a[mt][3], b.z, b.w);
        }
    }
    float* ui = u + (size_t)zl * 4096 * 32;
#pragma unroll
    for (int mt = 0; mt < 2; mt++) {
        int p0 = (R0 + row) * 64 + (ms * 2 + mt) * 16 + g;
#pragma unroll
        for (int nt = 0; nt < 4; nt++) {
            int oc = nt * 8 + tg * 2;
            *(float2*)&ui[(size_t)p0 * 32 + oc] = make_float2(acc[mt][nt][0], acc[mt][nt][1]);
            *(float2*)&ui[(size_t)(p0 + 8) * 32 + oc] = make_float2(acc[mt][nt][2], acc[mt][nt][3]);
        }
    }
}

// ---------------- 3x3 convs (SC2/SC3), mma.sync, 4-warp CTAs (r13 winner) ---------
template <int IC, int OC, int W, int MG, int NG>
__global__ void __launch_bounds__(32 * MG * NG)
conv3_k(const unsigned char* __restrict__ x, const uint4* __restrict__ B,
        float* __restrict__ u, int z0) {
    constexpr int XP = IC + 8;
    constexpr int SXW = W + 2;
    constexpr int SH = 6;                 // 4 rows + 2 halo
    constexpr int NT = 32 * MG * NG;
    constexpr int NICB = IC / 16, NTG = OC / 8;
    __shared__ __align__(16) __half xs[SH * SXW * XP];
    const int tid = threadIdx.x, lane = tid & 31, warp = tid >> 5;
    const int mg = warp % MG, ng = warp / MG;
    const int zl = blockIdx.y, R0 = blockIdx.x * 4;
    const unsigned char* xb = x + (size_t)(z0 + zl) * W * W * IC;
    for (int idx = tid; idx < SH * SXW * (IC / 4); idx += NT) {
        int c4 = idx % (IC / 4);
        int r = idx / (IC / 4);
        int sx = r % SXW, sy = r / SXW;
        int gy = R0 + sy - 1, gx = sx - 1;
        unsigned v = 0;
        if (gy >= 0 && gy < W && gx >= 0 && gx < W)
            v = *(const unsigned*)(xb + ((size_t)gy * W + gx) * IC + c4 * 4);
        unsigned lo = ((v & 0xffu) ? 0x3C00u : 0u) | ((v & 0xff00u) ? 0x3C000000u : 0u);
        unsigned hi = ((v & 0xff0000u) ? 0x3C00u : 0u) | ((v & 0xff000000u) ? 0x3C000000u : 0u);
        *(uint2*)&xs[(sy * SXW + sx) * XP + c4 * 4] = make_uint2(lo, hi);
    }
    __syncthreads();
    uint32_t xsu = (uint32_t)__cvta_generic_to_shared(xs);
    const int l15 = lane & 15, lc8 = (lane >> 4) * 8;
    uint32_t abase[4];
#pragma unroll
    for (int mt = 0; mt < 4; mt++) {
        int p = mg * 64 + mt * 16 + l15;
        int ly = p / W, lx = p % W;
        abase[mt] = xsu + ((ly * SXW + lx) * XP + lc8) * 2;
    }
    float acc[4][4][4];
#pragma unroll
    for (int mt = 0; mt < 4; mt++)
#pragma unroll
        for (int nt = 0; nt < 4; nt++)
#pragma unroll
            for (int i = 0; i < 4; i++) acc[mt][nt][i] = 0.f;
#pragma unroll
    for (int kh = 0; kh < 3; kh++)
#pragma unroll
        for (int kw = 0; kw < 3; kw++)
#pragma unroll
            for (int icb = 0; icb < NICB; icb++) {
                const int it = (kh * 3 + kw) * NICB + icb;
                const int aoff = ((kh * SXW + kw) * XP + icb * 16) * 2;
                uint32_t a[4][4];
#pragma unroll
                for (int mt = 0; mt < 4; mt++) ldm4(a[mt], abase[mt] + aoff);
#pragma unroll
                for (int nt = 0; nt < 4; nt++) {
                    int ntg = ng * 4 + nt;
                    uint4 b = B[(it * NTG + ntg) * 32 + lane];
#pragma unroll
                    for (int mt = 0; mt < 4; mt++)
                        mmah(acc[mt][nt], a[mt][0], a[mt][1], a[mt][2], a[mt][3], b.x, b.y);
#pragma unroll
                    for (int mt = 0; mt < 4; mt++)
                        mmah(acc[mt][nt], a[mt][0], a[mt][1], a[mt][2], a[mt][3], b.z, b.w);
                }
            }
    float* ui = u + (size_t)zl * W * W * OC;
    const int g = lane >> 2, tg = lane & 3;
#pragma unroll
    for (int mt = 0; mt < 4; mt++) {
        int p0 = R0 * W + mg * 64 + mt * 16 + g;
#pragma unroll
        for (int nt = 0; nt < 4; nt++) {
            int oc = ng * 32 + nt * 8 + tg * 2;
            *(float2*)&ui[(size_t)p0 * OC + oc] = make_float2(acc[mt][nt][0], acc[mt][nt][1]);
            *(float2*)&ui[(size_t)(p0 + 8) * OC + oc] = make_float2(acc[mt][nt][2], acc[mt][nt][3]);
        }
    }
}

// ---------------- SF4a tensor-core GEMM: [400x8192](u8) x [8192->512], split-K=8 --
__global__ void __launch_bounds__(256)
gemm4am_k(const unsigned char* __restrict__ x, const uint4* __restrict__ B,
          float* __restrict__ part) {
    constexpr int KP = 72;  // fp16 pitch
    __shared__ __align__(16) __half as[128 * KP];
    const int tid = threadIdx.x, lane = tid & 31, warp = tid >> 5;
    const int mg = warp & 1, ng4 = warp >> 1;
    const int M0 = blockIdx.y * 128, N0 = blockIdx.x * 128;
    const int k00 = blockIdx.z * 1024;
    const int l15 = lane & 15, lc8 = (lane >> 4) * 8;
    const int g = lane >> 2, tg = lane & 3;
    uint32_t asu = (uint32_t)__cvta_generic_to_shared(as);
    float acc[4][4][4];
#pragma unroll
    for (int mt = 0; mt < 4; mt++)
#pragma unroll
        for (int nt = 0; nt < 4; nt++)
#pragma unroll
            for (int i = 0; i < 4; i++) acc[mt][nt][i] = 0.f;

    for (int k0 = k00; k0 < k00 + 1024; k0 += 64) {
#pragma unroll
        for (int i = 0; i < 8; i++) {
            int pos = tid + i * 256;
            int row = pos >> 4, c4 = pos & 15;
            uchar4 v = *(const uchar4*)(x + (size_t)(M0 + row) * 8192 + k0 + c4 * 4);
            unsigned lo = (v.x ? 0x3C00u : 0u) | (v.y ? 0x3C000000u : 0u);
            unsigned hi = (v.z ? 0x3C00u : 0u) | (v.w ? 0x3C000000u : 0u);
            *(uint2*)&as[row * KP + c4 * 4] = make_uint2(lo, hi);
        }
        __syncthreads();
#pragma unroll
        for (int kc = 0; kc < 4; kc++) {
            int kb = (k0 >> 4) + kc;
            uint32_t a[4][4];
#pragma unroll
            for (int mt = 0; mt < 4; mt++)
                ldm4(a[mt], asu + (((mg * 64 + mt * 16 + l15) * KP) + lc8 + kc * 16) * 2);
#pragma unroll
            for (int nt = 0; nt < 4; nt++) {
                int ngg = (N0 >> 3) + ng4 * 4 + nt;
                uint4 b = B[(kb * 64 + ngg) * 32 + lane];
#pragma unroll
                for (int mt = 0; mt < 4; mt++)
                    mmah(acc[mt][nt], a[mt][0], a[mt][1], a[mt][2], a[mt][3], b.x, b.y);
#pragma unroll
                for (int mt = 0; mt < 4; mt++)
                    mmah(acc[mt][nt], a[mt][0], a[mt][1], a[mt][2], a[mt][3], b.z, b.w);
            }
        }
        __syncthreads();
    }
    float* pb = part + (size_t)blockIdx.z * 204800;
#pragma unroll
    for (int mt = 0; mt < 4; mt++) {
        int z0 = M0 + mg * 64 + mt * 16 + g;
#pragma unroll
        for (int nt = 0; nt < 4; nt++) {
            int col = N0 + ng4 * 32 + nt * 8 + tg * 2;
            if (z0 < 400)
                *(float2*)&pb[(size_t)z0 * 512 + col] = make_float2(acc[mt][nt][0], acc[mt][nt][1]);
            if (z0 + 8 < 400)
                *(float2*)&pb[(size_t)(z0 + 8) * 512 + col] = make_float2(acc[mt][nt][2], acc[mt][nt][3]);
        }
    }
}

// ---------------- SF4a fused reduce(8)+scan, smem-staged (64 neurons/block) -------
__global__ void __launch_bounds__(256) scan4a_k(const float* __restrict__ part,
                                                unsigned char* __restrict__ s) {
    __shared__ float us[64 * 101];
    const int tid = threadIdx.x;
    const int nb = blockIdx.x * 64;
    for (int i = tid; i < 6400; i += 256) {
        int t = i >> 6, nl = i & 63;
        size_t base = (size_t)t * 2048 + nb + nl;
        float c = 0.f;
#pragma unroll
        for (int j = 0; j < 8; j++) c += part[(size_t)j * 204800 + base];
        us[nl * 101 + t] = c;
    }
    __syncthreads();
    if (tid < 64) {
        float p1 = 0.f, p2 = 0.f, cp = 0.f, r1 = 0.f, r2 = 0.f, sp = 0.f;
        const float* un = &us[tid * 101];
        for (int t = 0; t < 100; t++) {
            float c = un[t];
            float uu = C2A * p1 - CA2 * p2 + CB1 * cp;
            float yy = C2A * r1 - CA2 * r2 + CB1 * sp;
            float ss = (uu - 20.0f * yy >= 10.0f) ? 1.0f : 0.0f;
            s[(size_t)t * 2048 + nb + tid] = (unsigned char)ss;
            p2 = p1; p1 = uu; cp = c;
            r2 = r1; r1 = yy; sp = ss;
        }
    }
}

// ---------------- SF4b GEMM: [400 x 512](u8) * [512 -> 11] -------------------------
__global__ void gemm4b_k(const unsigned char* __restrict__ x, const float* __restrict__ w,
                         float* __restrict__ u) {
    int tb = blockIdx.x;
    int wid = threadIdx.x >> 5, lid = threadIdx.x & 31;  // 11 warps
    const unsigned char* xr = x + (size_t)tb * 512;
    const float* wr = w + (size_t)wid * 512;
    float s = 0.f;
    for (int k = lid; k < 512; k += 32) s += (float)xr[k] * wr[k];
#pragma unroll
    for (int off = 16; off; off >>= 1) s += __shfl_xor_sync(0xffffffffu, s, off);
    if (lid == 0) u[tb * 11 + wid] = s;
}

// ---------------- final scan (smem-staged): u4b [t][b*11+o] -> d_out [b][11][t] ----
__global__ void scan_out_k(const float* __restrict__ u, float* __restrict__ out) {
    __shared__ float us[44 * 101];
    const int tid = threadIdx.x;
    for (int i = tid; i < 4400; i += 128) {
        int t = i / 44, n = i % 44;
        us[n * 101 + t] = u[i];
    }
    __syncthreads();
    if (tid < 44) {
        int b = tid / 11, o = tid % 11;
        const float* un = &us[tid * 101];
        float a1 = 0.f, a2 = 0.f, cp = 0.f, r1 = 0.f, r2 = 0.f, sp = 0.f;
        for (int t = 0; t < 100; t++) {
            float c = un[t];
            float uu = C2A * a1 - CA2 * a2 + CB1 * cp;
            float yy = C2A * r1 - CA2 * r2 + CB1 * sp;
            float ss = (uu - 20.0f * yy >= 10.0f) ? 1.0f : 0.0f;
            out[(b * 11 + o) * 100 + t] = ss;
            a2 = a1; a1 = uu; cp = c;
            r2 = r1; r1 = yy; sp = ss;
        }
    }
}

// ---------------- driver ----------------------------------------------------------
extern "C" void kernel_launch(void* const* d_in, const int* in_sizes, int n_in,
                              void* d_out, int out_size) {
    const float* s_in = (const float*)d_in[0];
    const float* w1   = (const float*)d_in[1];
    const float* w2   = (const float*)d_in[2];
    const float* w3   = (const float*)d_in[3];
    const float* wf4a = (const float*)d_in[4];
    const float* wf4b = (const float*)d_in[5];
    float* out = (float*)d_out;

    float *u, *pp, *st;
    unsigned char *sa, *sb;
    uint4 *b1, *b2, *b3, *b4;
    cudaGetSymbolAddress((void**)&u, g_u);
    cudaGetSymbolAddress((void**)&sa, g_s8a);
    cudaGetSymbolAddress((void**)&sb, g_s8b);
    cudaGetSymbolAddress((void**)&pp, g_part);
    cudaGetSymbolAddress((void**)&st, g_state);
    cudaGetSymbolAddress((void**)&b1, g_B1);
    cudaGetSymbolAddress((void**)&b2, g_B2);
    cudaGetSymbolAddress((void**)&b3, g_B3);
    cudaGetSymbolAddress((void**)&b4, g_B4);

    // launch order arranged so index 3 (the profiled launch) is conv1_k.
    prep4a_k<<<4096, 256>>>(wf4a, b4);                    // 0
    scan_in_k<<<128, 256>>>(s_in, sa);                    // 1
    prepB1_k<<<3, 256>>>(w1, b1);                         // 2

    // SC1: 4 t-chunks of 25; u slab (52 MB) stays L2-resident between conv and scan
    for (int ch = 0; ch < 4; ch++) {
        conv1_k<<<dim3(16, 100), 256>>>(sa, b1, u, ch * 100);   // ch0 -> index 3
        scanpool_k<32, 32, 32, false><<<512, 256>>>(u, sb, st, ch * 25, 25);
    }
    prepB3_k<32, 8, 2><<<18, 256>>>(w2, b2, 4608);
    prepB3_k<64, 16, 4><<<72, 256>>>(w3, b3, 18432);
    // SC2: 2 t-chunks of 50; u slab 52 MB
    for (int ch = 0; ch < 2; ch++) {
        conv3_k<32, 64, 32, 2, 2><<<dim3(8, 200), 128>>>(sb, b2, u, ch * 200);
        scanpool_k<64, 16, 16, false><<<256, 256>>>(u, sa, st, ch * 50, 50);
    }
    // SC3: single chunk (u = 52 MB total)
    conv3_k<64, 128, 16, 1, 4><<<dim3(4, 400), 128>>>(sa, b3, u, 0);
    scanpool_k<128, 8, 8, true><<<64, 256>>>(u, sb, st, 0, 100);

    // SF4a: tensor-core GEMM split-K=8 -> part; fused smem reduce+scan -> sa
    gemm4am_k<<<dim3(4, 4, 8), 256>>>(sb, b4, pp);
    scan4a_k<<<32, 256>>>(pp, sa);
    // SF4b: GEMM -> u : [z][11]; final scan -> d_out [4][11][100]
    gemm4b_k<<<400, 352>>>(sa, wf4b, u);
    scan_out_k<<<1, 128>>>(u, out);
}